// round 1
// baseline (speedup 1.0000x reference)
#include <cuda_runtime.h>
#include <cuda_bf16.h>
#include <math.h>

// Problem constants
#define BATCH   4
#define SEQ     2048
#define DMODEL  1024
#define NHEADS  16
#define DHEAD   64
#define MTOT    (BATCH * SEQ)   // 8192 rows

// ---------------------------------------------------------------------------
// Scratch (static device globals — allocation-free per harness rules)
// ---------------------------------------------------------------------------
__device__ float g_Q[MTOT * DMODEL];
__device__ float g_K[MTOT * DMODEL];
__device__ float g_V[MTOT * DMODEL];
__device__ float g_O[MTOT * DMODEL];

// ---------------------------------------------------------------------------
// SGEMM:  C[M,N] = A[M,K] * W[N,K]^T   (both row-major, NT form)
// 128x128 tile, BK=16, 256 threads, 8x8 micro-tile per thread.
// acode: 0 -> A = Aext, 1 -> A = g_O
// ccode: 0/1/2 -> g_Q/g_K/g_V, 3 -> Cext
// ---------------------------------------------------------------------------
__global__ __launch_bounds__(256) void sgemm_nt(const float* __restrict__ Aext,
                                                const float* __restrict__ W,
                                                float* __restrict__ Cext,
                                                int acode, int ccode)
{
    const int M = MTOT, N = DMODEL, K = DMODEL;
    (void)M;
    const float* __restrict__ A = (acode == 0) ? Aext : g_O;
    float* __restrict__ C =
        (ccode == 0) ? g_Q : (ccode == 1) ? g_K : (ccode == 2) ? g_V : Cext;

    __shared__ float As[16][132];   // [k][m], padded
    __shared__ float Bs[16][132];   // [k][n], padded

    const int bm = blockIdx.y * 128;
    const int bn = blockIdx.x * 128;
    const int tid = threadIdx.x;
    const int ty = tid >> 4;   // 0..15 (row group)
    const int tx = tid & 15;   // 0..15 (col group)

    float acc[8][8];
#pragma unroll
    for (int i = 0; i < 8; i++)
#pragma unroll
        for (int j = 0; j < 8; j++) acc[i][j] = 0.0f;

    for (int k0 = 0; k0 < K; k0 += 16) {
        // Cooperative loads: 128 rows x 16 cols for each operand.
#pragma unroll
        for (int i = 0; i < 2; i++) {
            int idx = tid + i * 256;        // 0..511
            int r   = idx >> 2;             // 0..127
            int c4  = idx & 3;              // 0..3 (float4 within 16 cols)
            float4 va = *(const float4*)(A + (size_t)(bm + r) * K + k0 + c4 * 4);
            As[c4 * 4 + 0][r] = va.x;
            As[c4 * 4 + 1][r] = va.y;
            As[c4 * 4 + 2][r] = va.z;
            As[c4 * 4 + 3][r] = va.w;
            float4 vb = *(const float4*)(W + (size_t)(bn + r) * K + k0 + c4 * 4);
            Bs[c4 * 4 + 0][r] = vb.x;
            Bs[c4 * 4 + 1][r] = vb.y;
            Bs[c4 * 4 + 2][r] = vb.z;
            Bs[c4 * 4 + 3][r] = vb.w;
        }
        __syncthreads();

#pragma unroll
        for (int kk = 0; kk < 16; kk++) {
            float a[8], b[8];
#pragma unroll
            for (int i = 0; i < 8; i++) a[i] = As[kk][ty * 8 + i];
#pragma unroll
            for (int j = 0; j < 8; j++) b[j] = Bs[kk][tx * 8 + j];
#pragma unroll
            for (int i = 0; i < 8; i++)
#pragma unroll
                for (int j = 0; j < 8; j++) acc[i][j] += a[i] * b[j];
        }
        __syncthreads();
    }

#pragma unroll
    for (int i = 0; i < 8; i++) {
        float* crow = C + (size_t)(bm + ty * 8 + i) * N + bn + tx * 8;
#pragma unroll
        for (int j = 0; j < 8; j += 4) {
            float4 v = make_float4(acc[i][j], acc[i][j + 1], acc[i][j + 2], acc[i][j + 3]);
            *(float4*)(crow + j) = v;
        }
    }
}

// ---------------------------------------------------------------------------
// Flash attention (causal), fp32.
// Grid: (SEQ/128, NHEADS, BATCH), Block: 128 threads.
// Each thread owns one query row (q[64] in regs, acc[64] in regs).
// K/V tiles (64 x 64) staged in smem; online softmax in 16-score chunks.
// ---------------------------------------------------------------------------
#define AT_BR 128
#define AT_BC 64

__global__ __launch_bounds__(128) void flash_attn_causal()
{
    __shared__ float Ksh[AT_BC][DHEAD];   // 16 KB
    __shared__ float Vsh[AT_BC][DHEAD];   // 16 KB

    const int qt  = blockIdx.x;
    const int h   = blockIdx.y;
    const int b   = blockIdx.z;
    const int tid = threadIdx.x;

    const int   row   = qt * AT_BR + tid;        // global query position in seq
    const float scale = 0.125f;                  // 1/sqrt(64)

    const size_t head_off = (size_t)h * DHEAD;
    const size_t bbase    = (size_t)b * SEQ;

    // --- Load my q row (stage via Ksh for coalescing) -----------------------
    float q[DHEAD];
    {
        // 128 rows x 64 cols = 2048 float4; stage in two 64-row halves.
#pragma unroll
        for (int half = 0; half < 2; half++) {
#pragma unroll
            for (int l = 0; l < 8; l++) {
                int idx = tid + l * 128;     // 0..1023 float4 slots
                int r   = idx >> 4;          // 0..63
                int c4  = idx & 15;          // 0..15
                float4 v = *(const float4*)(g_Q + (bbase + qt * AT_BR + half * 64 + r) * DMODEL
                                            + head_off + c4 * 4);
                *(float4*)&Ksh[r][c4 * 4] = v;
            }
            __syncthreads();
            if ((tid >> 6) == half) {
                int r = tid & 63;
#pragma unroll
                for (int d = 0; d < DHEAD; d++) q[d] = Ksh[r][d];
            }
            __syncthreads();
        }
    }

    float acc[DHEAD];
#pragma unroll
    for (int d = 0; d < DHEAD; d++) acc[d] = 0.0f;
    float m = -1e30f;
    float lsum = 0.0f;

    const int ktmax = (qt * AT_BR + AT_BR - 1) / AT_BC;   // inclusive

    for (int kt = 0; kt <= ktmax; kt++) {
        // --- Cooperative coalesced load of K and V tiles (64x64 each) ------
#pragma unroll
        for (int l = 0; l < 8; l++) {
            int idx = tid + l * 128;     // 0..1023
            int r   = idx >> 4;          // 0..63
            int c4  = idx & 15;          // 0..15
            size_t gofs = (bbase + kt * AT_BC + r) * DMODEL + head_off + c4 * 4;
            *(float4*)&Ksh[r][c4 * 4] = *(const float4*)(g_K + gofs);
            *(float4*)&Vsh[r][c4 * 4] = *(const float4*)(g_V + gofs);
        }
        __syncthreads();

        // --- Process tile in 4 chunks of 16 scores -------------------------
#pragma unroll
        for (int g = 0; g < 4; g++) {
            float s[16];
            float mt = -1e30f;
#pragma unroll
            for (int jj = 0; jj < 16; jj++) {
                int j = g * 16 + jj;
                float acc_s = 0.0f;
#pragma unroll
                for (int d = 0; d < DHEAD; d += 4) {
                    float4 k4 = *(const float4*)&Ksh[j][d];
                    acc_s += q[d] * k4.x + q[d + 1] * k4.y
                           + q[d + 2] * k4.z + q[d + 3] * k4.w;
                }
                acc_s *= scale;
                int kpos = kt * AT_BC + j;
                if (kpos > row) acc_s = -1e30f;    // causal mask
                s[jj] = acc_s;
                mt = fmaxf(mt, acc_s);
            }

            float mnew = fmaxf(m, mt);
            float corr = __expf(m - mnew);
            lsum *= corr;
#pragma unroll
            for (int d = 0; d < DHEAD; d++) acc[d] *= corr;
            m = mnew;

#pragma unroll
            for (int jj = 0; jj < 16; jj++) {
                int j = g * 16 + jj;
                float p = __expf(s[jj] - m);
                lsum += p;
#pragma unroll
                for (int d = 0; d < DHEAD; d += 4) {
                    float4 v4 = *(const float4*)&Vsh[j][d];
                    acc[d]     += p * v4.x;
                    acc[d + 1] += p * v4.y;
                    acc[d + 2] += p * v4.z;
                    acc[d + 3] += p * v4.w;
                }
            }
        }
        __syncthreads();
    }

    // --- Write normalized output row ---------------------------------------
    float inv = 1.0f / lsum;
    float* orow = g_O + (bbase + row) * DMODEL + head_off;
#pragma unroll
    for (int d = 0; d < DHEAD; d += 4) {
        float4 v = make_float4(acc[d] * inv, acc[d + 1] * inv,
                               acc[d + 2] * inv, acc[d + 3] * inv);
        *(float4*)(orow + d) = v;
    }
}

// ---------------------------------------------------------------------------
// Launch
// ---------------------------------------------------------------------------
extern "C" void kernel_launch(void* const* d_in, const int* in_sizes, int n_in,
                              void* d_out, int out_size)
{
    const float* x  = (const float*)d_in[0];
    const float* wq = (const float*)d_in[1];
    const float* wk = (const float*)d_in[2];
    const float* wv = (const float*)d_in[3];
    const float* wo = (const float*)d_in[4];
    float* out = (float*)d_out;

    dim3 ggrid(DMODEL / 128, MTOT / 128);   // (8, 64)
    dim3 gblk(256);

    sgemm_nt<<<ggrid, gblk>>>(x, wq, nullptr, 0, 0);   // g_Q = x @ wq^T
    sgemm_nt<<<ggrid, gblk>>>(x, wk, nullptr, 0, 1);   // g_K = x @ wk^T
    sgemm_nt<<<ggrid, gblk>>>(x, wv, nullptr, 0, 2);   // g_V = x @ wv^T

    dim3 agrid(SEQ / AT_BR, NHEADS, BATCH);            // (16, 16, 4)
    flash_attn_causal<<<agrid, 128>>>();               // g_O = attention

    sgemm_nt<<<ggrid, gblk>>>(nullptr, wo, out, 1, 3); // out = g_O @ wo^T
}

// round 2
// speedup vs baseline: 4.7352x; 4.7352x over previous
#include <cuda_runtime.h>
#include <cuda_bf16.h>
#include <math.h>

#define BATCH   4
#define SEQ     2048
#define DMODEL  1024
#define NHEADS  16
#define DHEAD   64
#define MTOT    (BATCH * SEQ)

// ---------------------------------------------------------------------------
// Scratch
// ---------------------------------------------------------------------------
__device__ float g_Q[MTOT * DMODEL];
__device__ float g_K[MTOT * DMODEL];
__device__ float g_V[MTOT * DMODEL];
__device__ float g_O[MTOT * DMODEL];

// ---------------------------------------------------------------------------
// Helpers
// ---------------------------------------------------------------------------
__device__ __forceinline__ unsigned f2tf(float f) {
    unsigned u;
    asm("cvt.rna.tf32.f32 %0, %1;" : "=r"(u) : "f"(f));
    return u;
}

__device__ __forceinline__ void mma_tf32(float c[4],
                                         unsigned a0, unsigned a1, unsigned a2, unsigned a3,
                                         unsigned b0, unsigned b1) {
    asm volatile(
        "mma.sync.aligned.m16n8k8.row.col.f32.tf32.tf32.f32 "
        "{%0,%1,%2,%3}, {%4,%5,%6,%7}, {%8,%9}, {%0,%1,%2,%3};"
        : "+f"(c[0]), "+f"(c[1]), "+f"(c[2]), "+f"(c[3])
        : "r"(a0), "r"(a1), "r"(a2), "r"(a3), "r"(b0), "r"(b1));
}

__device__ __forceinline__ void st_tf4(unsigned* p, float4 v) {
    uint4 t;
    t.x = f2tf(v.x); t.y = f2tf(v.y); t.z = f2tf(v.z); t.w = f2tf(v.w);
    *(uint4*)p = t;
}

// ---------------------------------------------------------------------------
// TF32 GEMM:  C[M,N] = A[M,K] * W[N,K]^T   (M=8192, N=K=1024)
// 128x128x16 tile, 256 threads (8 warps as 4x2), warp tile 32x64.
// smem stride 20 floats -> fragment LDS bank-conflict-free.
// ---------------------------------------------------------------------------
#define GSTR 20

__global__ __launch_bounds__(256) void gemm_tf32(const float* __restrict__ Aext,
                                                 const float* __restrict__ W,
                                                 float* __restrict__ Cext,
                                                 int acode, int ccode)
{
    const float* __restrict__ A = (acode == 0) ? Aext : g_O;
    float* __restrict__ C =
        (ccode == 0) ? g_Q : (ccode == 1) ? g_K : (ccode == 2) ? g_V : Cext;

    __shared__ unsigned As[2][128 * GSTR];
    __shared__ unsigned Bs[2][128 * GSTR];

    const int tid  = threadIdx.x;
    const int lane = tid & 31;
    const int warp = tid >> 5;
    const int wm   = (warp >> 1) * 32;   // 0,32,64,96
    const int wn   = (warp & 1) * 64;    // 0,64
    const int lr   = lane >> 2;          // 0..7
    const int lc   = lane & 3;           // 0..3

    const int bm = blockIdx.y * 128;
    const int bn = blockIdx.x * 128;

    const int lrow = tid >> 2;           // 0..63
    const int lc4  = (tid & 3) * 4;      // 0,4,8,12

    const float* Ag = A + (size_t)(bm + lrow) * DMODEL + lc4;
    const float* Wg = W + (size_t)(bn + lrow) * DMODEL + lc4;

    float acc[2][8][4];
#pragma unroll
    for (int mi = 0; mi < 2; mi++)
#pragma unroll
        for (int ni = 0; ni < 8; ni++)
#pragma unroll
            for (int e = 0; e < 4; e++) acc[mi][ni][e] = 0.0f;

    float4 ra0 = *(const float4*)(Ag);
    float4 ra1 = *(const float4*)(Ag + (size_t)64 * DMODEL);
    float4 rb0 = *(const float4*)(Wg);
    float4 rb1 = *(const float4*)(Wg + (size_t)64 * DMODEL);

    int buf = 0;
    for (int k0 = 0; k0 < DMODEL; k0 += 16) {
        st_tf4(&As[buf][lrow * GSTR + lc4], ra0);
        st_tf4(&As[buf][(lrow + 64) * GSTR + lc4], ra1);
        st_tf4(&Bs[buf][lrow * GSTR + lc4], rb0);
        st_tf4(&Bs[buf][(lrow + 64) * GSTR + lc4], rb1);
        __syncthreads();

        if (k0 + 16 < DMODEL) {
            ra0 = *(const float4*)(Ag + k0 + 16);
            ra1 = *(const float4*)(Ag + k0 + 16 + (size_t)64 * DMODEL);
            rb0 = *(const float4*)(Wg + k0 + 16);
            rb1 = *(const float4*)(Wg + k0 + 16 + (size_t)64 * DMODEL);
        }

#pragma unroll
        for (int ks = 0; ks < 2; ks++) {
            const int kk = ks * 8;
            unsigned af[2][4];
#pragma unroll
            for (int mi = 0; mi < 2; mi++) {
                int r = wm + mi * 16 + lr;
                af[mi][0] = As[buf][r * GSTR + kk + lc];
                af[mi][1] = As[buf][(r + 8) * GSTR + kk + lc];
                af[mi][2] = As[buf][r * GSTR + kk + lc + 4];
                af[mi][3] = As[buf][(r + 8) * GSTR + kk + lc + 4];
            }
            unsigned bf[8][2];
#pragma unroll
            for (int ni = 0; ni < 8; ni++) {
                int r = wn + ni * 8 + lr;
                bf[ni][0] = Bs[buf][r * GSTR + kk + lc];
                bf[ni][1] = Bs[buf][r * GSTR + kk + lc + 4];
            }
#pragma unroll
            for (int mi = 0; mi < 2; mi++)
#pragma unroll
                for (int ni = 0; ni < 8; ni++)
                    mma_tf32(acc[mi][ni], af[mi][0], af[mi][1], af[mi][2], af[mi][3],
                             bf[ni][0], bf[ni][1]);
        }
        __syncthreads();
        buf ^= 1;
    }

#pragma unroll
    for (int mi = 0; mi < 2; mi++) {
#pragma unroll
        for (int ni = 0; ni < 8; ni++) {
            int row0 = bm + wm + mi * 16 + lr;
            int col  = bn + wn + ni * 8 + 2 * lc;
            float2 v0 = make_float2(acc[mi][ni][0], acc[mi][ni][1]);
            float2 v1 = make_float2(acc[mi][ni][2], acc[mi][ni][3]);
            *(float2*)(C + (size_t)row0 * DMODEL + col) = v0;
            *(float2*)(C + (size_t)(row0 + 8) * DMODEL + col) = v1;
        }
    }
}

// ---------------------------------------------------------------------------
// TF32 flash attention (causal). Br=64 (4 warps x m16), Bc=64.
// Q fragments in registers; K/V staged in padded smem (tf32);
// P round-trips through warp-private smem rows (reuses Q staging buffer).
// ---------------------------------------------------------------------------
#define KSTR 68
#define VSTR 72
#define AT_SMEM ((64 * KSTR + 64 * VSTR + 64 * KSTR) * 4)

__global__ __launch_bounds__(128) void flash_tf32()
{
    extern __shared__ unsigned sm[];
    unsigned* Ksh = sm;                          // [64][68]
    unsigned* Vsh = sm + 64 * KSTR;              // [64][72]
    unsigned* PQ  = sm + 64 * KSTR + 64 * VSTR;  // [64][68]  Q staging, then P

    const int qt   = gridDim.x - 1 - blockIdx.x;   // heavy blocks first
    const int h    = blockIdx.y;
    const int b    = blockIdx.z;
    const int tid  = threadIdx.x;
    const int lane = tid & 31;
    const int warp = tid >> 5;
    const int lr   = lane >> 2;
    const int lc   = lane & 3;

    const size_t bbase = (size_t)b * SEQ;
    const size_t hoff  = (size_t)h * DHEAD;

    // --- stage Q (tf32) and extract register A-fragments --------------------
#pragma unroll
    for (int l = 0; l < 8; l++) {
        int idx = tid + l * 128;
        int r   = idx >> 4;
        int c4  = (idx & 15) * 4;
        float4 v = *(const float4*)(g_Q + (bbase + qt * 64 + r) * DMODEL + hoff + c4);
        st_tf4(&PQ[r * KSTR + c4], v);
    }
    __syncthreads();

    unsigned qf[8][4];
    const int qlr = warp * 16 + lr;
#pragma unroll
    for (int kt = 0; kt < 8; kt++) {
        qf[kt][0] = PQ[qlr * KSTR + kt * 8 + lc];
        qf[kt][1] = PQ[(qlr + 8) * KSTR + kt * 8 + lc];
        qf[kt][2] = PQ[qlr * KSTR + kt * 8 + lc + 4];
        qf[kt][3] = PQ[(qlr + 8) * KSTR + kt * 8 + lc + 4];
    }
    __syncthreads();   // PQ now free for P

    float o[8][4];
#pragma unroll
    for (int ni = 0; ni < 8; ni++)
#pragma unroll
        for (int e = 0; e < 4; e++) o[ni][e] = 0.0f;

    float m0 = -1e30f, m1 = -1e30f, l0 = 0.0f, l1 = 0.0f;
    const int q0 = qt * 64 + warp * 16 + lr;
    const int q1 = q0 + 8;

    for (int t = 0; t <= qt; t++) {
        // --- stage K/V tile (tf32) ------------------------------------------
#pragma unroll
        for (int l = 0; l < 8; l++) {
            int idx = tid + l * 128;
            int r   = idx >> 4;
            int c4  = (idx & 15) * 4;
            size_t g = (bbase + t * 64 + r) * DMODEL + hoff + c4;
            st_tf4(&Ksh[r * KSTR + c4], *(const float4*)(g_K + g));
            st_tf4(&Vsh[r * VSTR + c4], *(const float4*)(g_V + g));
        }
        __syncthreads();

        // --- S = Q @ K^T -----------------------------------------------------
        float s[8][4];
#pragma unroll
        for (int ni = 0; ni < 8; ni++) {
#pragma unroll
            for (int e = 0; e < 4; e++) s[ni][e] = 0.0f;
#pragma unroll
            for (int kt = 0; kt < 8; kt++) {
                unsigned b0 = Ksh[(ni * 8 + lr) * KSTR + kt * 8 + lc];
                unsigned b1 = Ksh[(ni * 8 + lr) * KSTR + kt * 8 + lc + 4];
                mma_tf32(s[ni], qf[kt][0], qf[kt][1], qf[kt][2], qf[kt][3], b0, b1);
            }
        }

        // --- scale + causal mask + row max ----------------------------------
        const bool diag = (t == qt);
        float mt0 = -1e30f, mt1 = -1e30f;
#pragma unroll
        for (int ni = 0; ni < 8; ni++) {
            int kc = t * 64 + ni * 8 + 2 * lc;
#pragma unroll
            for (int e = 0; e < 4; e++) s[ni][e] *= 0.125f;
            if (diag) {
                if (kc     > q0) s[ni][0] = -1e30f;
                if (kc + 1 > q0) s[ni][1] = -1e30f;
                if (kc     > q1) s[ni][2] = -1e30f;
                if (kc + 1 > q1) s[ni][3] = -1e30f;
            }
            mt0 = fmaxf(mt0, fmaxf(s[ni][0], s[ni][1]));
            mt1 = fmaxf(mt1, fmaxf(s[ni][2], s[ni][3]));
        }
        mt0 = fmaxf(mt0, __shfl_xor_sync(0xffffffffu, mt0, 1));
        mt0 = fmaxf(mt0, __shfl_xor_sync(0xffffffffu, mt0, 2));
        mt1 = fmaxf(mt1, __shfl_xor_sync(0xffffffffu, mt1, 1));
        mt1 = fmaxf(mt1, __shfl_xor_sync(0xffffffffu, mt1, 2));

        float mn0 = fmaxf(m0, mt0), mn1 = fmaxf(m1, mt1);
        float cr0 = __expf(m0 - mn0), cr1 = __expf(m1 - mn1);
        m0 = mn0; m1 = mn1;
        l0 *= cr0; l1 *= cr1;
#pragma unroll
        for (int ni = 0; ni < 8; ni++) {
            o[ni][0] *= cr0; o[ni][1] *= cr0;
            o[ni][2] *= cr1; o[ni][3] *= cr1;
        }

        // --- P = exp(S - m), write warp-private smem rows --------------------
        float ps0 = 0.0f, ps1 = 0.0f;
        const int pr0 = warp * 16 + lr;
#pragma unroll
        for (int ni = 0; ni < 8; ni++) {
            float p0 = __expf(s[ni][0] - m0);
            float p1 = __expf(s[ni][1] - m0);
            float p2 = __expf(s[ni][2] - m1);
            float p3 = __expf(s[ni][3] - m1);
            ps0 += p0 + p1; ps1 += p2 + p3;
            PQ[pr0 * KSTR + ni * 8 + 2 * lc]           = f2tf(p0);
            PQ[pr0 * KSTR + ni * 8 + 2 * lc + 1]       = f2tf(p1);
            PQ[(pr0 + 8) * KSTR + ni * 8 + 2 * lc]     = f2tf(p2);
            PQ[(pr0 + 8) * KSTR + ni * 8 + 2 * lc + 1] = f2tf(p3);
        }
        ps0 += __shfl_xor_sync(0xffffffffu, ps0, 1);
        ps0 += __shfl_xor_sync(0xffffffffu, ps0, 2);
        ps1 += __shfl_xor_sync(0xffffffffu, ps1, 1);
        ps1 += __shfl_xor_sync(0xffffffffu, ps1, 2);
        l0 += ps0; l1 += ps1;
        __syncwarp();

        // --- O += P @ V ------------------------------------------------------
#pragma unroll
        for (int kk = 0; kk < 8; kk++) {
            unsigned pa0 = PQ[pr0 * KSTR + kk * 8 + lc];
            unsigned pa1 = PQ[(pr0 + 8) * KSTR + kk * 8 + lc];
            unsigned pa2 = PQ[pr0 * KSTR + kk * 8 + lc + 4];
            unsigned pa3 = PQ[(pr0 + 8) * KSTR + kk * 8 + lc + 4];
#pragma unroll
            for (int ni = 0; ni < 8; ni++) {
                unsigned vb0 = Vsh[(kk * 8 + lc) * VSTR + ni * 8 + lr];
                unsigned vb1 = Vsh[(kk * 8 + lc + 4) * VSTR + ni * 8 + lr];
                mma_tf32(o[ni], pa0, pa1, pa2, pa3, vb0, vb1);
            }
        }
        __syncthreads();   // before next tile restages K/V
    }

    // --- normalize + store ---------------------------------------------------
    float i0 = 1.0f / l0, i1 = 1.0f / l1;
#pragma unroll
    for (int ni = 0; ni < 8; ni++) {
        int col = ni * 8 + 2 * lc;
        float2 v0 = make_float2(o[ni][0] * i0, o[ni][1] * i0);
        float2 v1 = make_float2(o[ni][2] * i1, o[ni][3] * i1);
        *(float2*)(g_O + (bbase + q0) * DMODEL + hoff + col) = v0;
        *(float2*)(g_O + (bbase + q1) * DMODEL + hoff + col) = v1;
    }
}

// ---------------------------------------------------------------------------
// Launch
// ---------------------------------------------------------------------------
extern "C" void kernel_launch(void* const* d_in, const int* in_sizes, int n_in,
                              void* d_out, int out_size)
{
    const float* x  = (const float*)d_in[0];
    const float* wq = (const float*)d_in[1];
    const float* wk = (const float*)d_in[2];
    const float* wv = (const float*)d_in[3];
    const float* wo = (const float*)d_in[4];
    float* out = (float*)d_out;

    cudaFuncSetAttribute(flash_tf32, cudaFuncAttributeMaxDynamicSharedMemorySize, AT_SMEM);

    dim3 ggrid(DMODEL / 128, MTOT / 128);   // (8, 64)
    gemm_tf32<<<ggrid, 256>>>(x, wq, nullptr, 0, 0);
    gemm_tf32<<<ggrid, 256>>>(x, wk, nullptr, 0, 1);
    gemm_tf32<<<ggrid, 256>>>(x, wv, nullptr, 0, 2);

    dim3 agrid(SEQ / 64, NHEADS, BATCH);    // (32, 16, 4)
    flash_tf32<<<agrid, 128, AT_SMEM>>>();

    gemm_tf32<<<ggrid, 256>>>(nullptr, wo, out, 1, 3);
}

// round 4
// speedup vs baseline: 7.3331x; 1.5487x over previous
#include <cuda_runtime.h>
#include <cuda_fp16.h>
#include <cstdint>
#include <math.h>

#define BATCH   4
#define SEQ     2048
#define DMODEL  1024
#define NHEADS  16
#define DHEAD   64
#define MTOT    (BATCH * SEQ)

// ---------------------------------------------------------------------------
// Scratch
// ---------------------------------------------------------------------------
__device__ float g_Q[MTOT * DMODEL];
__device__ float g_K[MTOT * DMODEL];
__device__ float g_V[MTOT * DMODEL];
__device__ float g_O[MTOT * DMODEL];

// ---------------------------------------------------------------------------
// Helpers
// ---------------------------------------------------------------------------
__device__ __forceinline__ unsigned pack_h2(float lo, float hi) {
    __half2 h = __floats2half2_rn(lo, hi);
    return *(unsigned*)&h;
}

__device__ __forceinline__ void mma_f16(float c[4],
                                        unsigned a0, unsigned a1, unsigned a2, unsigned a3,
                                        unsigned b0, unsigned b1) {
    asm volatile(
        "mma.sync.aligned.m16n8k16.row.col.f32.f16.f16.f32 "
        "{%0,%1,%2,%3}, {%4,%5,%6,%7}, {%8,%9}, {%0,%1,%2,%3};"
        : "+f"(c[0]), "+f"(c[1]), "+f"(c[2]), "+f"(c[3])
        : "r"(a0), "r"(a1), "r"(a2), "r"(a3), "r"(b0), "r"(b1));
}

// ---------------------------------------------------------------------------
// FP16 GEMM:  C[M,N] = A[M,K] * W[N,K]^T   (M=8192, N=K=1024)
// 128x128x16 tile, 256 threads (8 warps as 4x2), warp tile 32x64.
// smem row stride = 12 words (24 halves) -> all fragment LDS conflict-free.
// qkv mode: blockIdx.z selects W (wq/wk/wv) and C (g_Q/g_K/g_V).
// ---------------------------------------------------------------------------
#define GSTRW 12

__global__ __launch_bounds__(256) void gemm_f16(const float* __restrict__ Aext,
                                                const float* __restrict__ W0,
                                                const float* __restrict__ W1,
                                                const float* __restrict__ W2,
                                                float* __restrict__ Cext,
                                                int mode)   // 0 = qkv (z picks), 1 = out-proj
{
    __shared__ unsigned As[2][128 * GSTRW];
    __shared__ unsigned Bs[2][128 * GSTRW];

    const int z = blockIdx.z;
    const float* __restrict__ A = (mode == 0) ? Aext : g_O;
    const float* __restrict__ W = (z == 0) ? W0 : (z == 1) ? W1 : W2;
    float* __restrict__ C =
        (mode == 1) ? Cext : (z == 0) ? g_Q : (z == 1) ? g_K : g_V;

    const int tid  = threadIdx.x;
    const int lane = tid & 31;
    const int warp = tid >> 5;
    const int wm   = (warp >> 1) * 32;
    const int wn   = (warp & 1) * 64;
    const int lr   = lane >> 2;
    const int lc   = lane & 3;

    const int bm = blockIdx.y * 128;
    const int bn = blockIdx.x * 128;

    const int lrow = tid >> 2;           // 0..63
    const int lc4  = (tid & 3) * 4;      // 0,4,8,12

    const float* Ag = A + (size_t)(bm + lrow) * DMODEL + lc4;
    const float* Wg = W + (size_t)(bn + lrow) * DMODEL + lc4;

    float acc[2][8][4];
#pragma unroll
    for (int mi = 0; mi < 2; mi++)
#pragma unroll
        for (int ni = 0; ni < 8; ni++)
#pragma unroll
            for (int e = 0; e < 4; e++) acc[mi][ni][e] = 0.0f;

    float4 ra0 = *(const float4*)(Ag);
    float4 ra1 = *(const float4*)(Ag + (size_t)64 * DMODEL);
    float4 rb0 = *(const float4*)(Wg);
    float4 rb1 = *(const float4*)(Wg + (size_t)64 * DMODEL);

    int buf = 0;
    const int w0 = lrow * GSTRW + lc4 / 2;
    for (int k0 = 0; k0 < DMODEL; k0 += 16) {
        As[buf][w0]     = pack_h2(ra0.x, ra0.y);
        As[buf][w0 + 1] = pack_h2(ra0.z, ra0.w);
        As[buf][w0 + 64 * GSTRW]     = pack_h2(ra1.x, ra1.y);
        As[buf][w0 + 64 * GSTRW + 1] = pack_h2(ra1.z, ra1.w);
        Bs[buf][w0]     = pack_h2(rb0.x, rb0.y);
        Bs[buf][w0 + 1] = pack_h2(rb0.z, rb0.w);
        Bs[buf][w0 + 64 * GSTRW]     = pack_h2(rb1.x, rb1.y);
        Bs[buf][w0 + 64 * GSTRW + 1] = pack_h2(rb1.z, rb1.w);
        __syncthreads();

        if (k0 + 16 < DMODEL) {
            ra0 = *(const float4*)(Ag + k0 + 16);
            ra1 = *(const float4*)(Ag + k0 + 16 + (size_t)64 * DMODEL);
            rb0 = *(const float4*)(Wg + k0 + 16);
            rb1 = *(const float4*)(Wg + k0 + 16 + (size_t)64 * DMODEL);
        }

        unsigned af[2][4];
#pragma unroll
        for (int mi = 0; mi < 2; mi++) {
            int r = wm + mi * 16 + lr;
            af[mi][0] = As[buf][r * GSTRW + lc];
            af[mi][1] = As[buf][(r + 8) * GSTRW + lc];
            af[mi][2] = As[buf][r * GSTRW + lc + 4];
            af[mi][3] = As[buf][(r + 8) * GSTRW + lc + 4];
        }
        unsigned bf[8][2];
#pragma unroll
        for (int ni = 0; ni < 8; ni++) {
            int r = wn + ni * 8 + lr;
            bf[ni][0] = Bs[buf][r * GSTRW + lc];
            bf[ni][1] = Bs[buf][r * GSTRW + lc + 4];
        }
#pragma unroll
        for (int mi = 0; mi < 2; mi++)
#pragma unroll
            for (int ni = 0; ni < 8; ni++)
                mma_f16(acc[mi][ni], af[mi][0], af[mi][1], af[mi][2], af[mi][3],
                        bf[ni][0], bf[ni][1]);
        __syncthreads();
        buf ^= 1;
    }

#pragma unroll
    for (int mi = 0; mi < 2; mi++) {
#pragma unroll
        for (int ni = 0; ni < 8; ni++) {
            int row0 = bm + wm + mi * 16 + lr;
            int col  = bn + wn + ni * 8 + 2 * lc;
            *(float2*)(C + (size_t)row0 * DMODEL + col) =
                make_float2(acc[mi][ni][0], acc[mi][ni][1]);
            *(float2*)(C + (size_t)(row0 + 8) * DMODEL + col) =
                make_float2(acc[mi][ni][2], acc[mi][ni][3]);
        }
    }
}

// ---------------------------------------------------------------------------
// FP16 flash attention (causal). Br=64 (4 warps x m16), Bc=64.
// Q/K/V/P staged as packed half2 words, row stride 36 words (72 halves).
// ---------------------------------------------------------------------------
#define FSTRW 36

__global__ __launch_bounds__(128) void flash_f16()
{
    __shared__ unsigned Ksh[64 * FSTRW];
    __shared__ unsigned Vsh[64 * FSTRW];
    __shared__ unsigned PQ [64 * FSTRW];

    const int qt   = gridDim.x - 1 - blockIdx.x;   // heavy blocks first
    const int h    = blockIdx.y;
    const int b    = blockIdx.z;
    const int tid  = threadIdx.x;
    const int lane = tid & 31;
    const int warp = tid >> 5;
    const int lr   = lane >> 2;
    const int lc   = lane & 3;

    const size_t bbase = (size_t)b * SEQ;
    const size_t hoff  = (size_t)h * DHEAD;

    // --- stage Q, extract register A-fragments -------------------------------
#pragma unroll
    for (int l = 0; l < 8; l++) {
        int idx = tid + l * 128;
        int r   = idx >> 4;
        int c4  = (idx & 15) * 4;
        float4 v = *(const float4*)(g_Q + (bbase + qt * 64 + r) * DMODEL + hoff + c4);
        PQ[r * FSTRW + c4 / 2]     = pack_h2(v.x, v.y);
        PQ[r * FSTRW + c4 / 2 + 1] = pack_h2(v.z, v.w);
    }
    __syncthreads();

    unsigned qf[4][4];
    const int qlr = warp * 16 + lr;
#pragma unroll
    for (int kt = 0; kt < 4; kt++) {
        qf[kt][0] = PQ[qlr * FSTRW + kt * 8 + lc];
        qf[kt][1] = PQ[(qlr + 8) * FSTRW + kt * 8 + lc];
        qf[kt][2] = PQ[qlr * FSTRW + kt * 8 + lc + 4];
        qf[kt][3] = PQ[(qlr + 8) * FSTRW + kt * 8 + lc + 4];
    }
    __syncthreads();   // PQ now free for P

    float o[8][4];
#pragma unroll
    for (int ni = 0; ni < 8; ni++)
#pragma unroll
        for (int e = 0; e < 4; e++) o[ni][e] = 0.0f;

    float m0 = -1e30f, m1 = -1e30f, l0 = 0.0f, l1 = 0.0f;
    const int q0 = qt * 64 + warp * 16 + lr;
    const int q1 = q0 + 8;

    const unsigned short* Vu = (const unsigned short*)Vsh;

    for (int t = 0; t <= qt; t++) {
        // --- stage K/V tile ---------------------------------------------------
#pragma unroll
        for (int l = 0; l < 8; l++) {
            int idx = tid + l * 128;
            int r   = idx >> 4;
            int c4  = (idx & 15) * 4;
            size_t g = (bbase + t * 64 + r) * DMODEL + hoff + c4;
            float4 kv = *(const float4*)(g_K + g);
            float4 vv = *(const float4*)(g_V + g);
            Ksh[r * FSTRW + c4 / 2]     = pack_h2(kv.x, kv.y);
            Ksh[r * FSTRW + c4 / 2 + 1] = pack_h2(kv.z, kv.w);
            Vsh[r * FSTRW + c4 / 2]     = pack_h2(vv.x, vv.y);
            Vsh[r * FSTRW + c4 / 2 + 1] = pack_h2(vv.z, vv.w);
        }
        __syncthreads();

        // --- S = Q @ K^T ------------------------------------------------------
        float s[8][4];
#pragma unroll
        for (int ni = 0; ni < 8; ni++) {
#pragma unroll
            for (int e = 0; e < 4; e++) s[ni][e] = 0.0f;
            const int n = ni * 8 + lr;
#pragma unroll
            for (int kt = 0; kt < 4; kt++) {
                unsigned b0 = Ksh[n * FSTRW + kt * 8 + lc];
                unsigned b1 = Ksh[n * FSTRW + kt * 8 + lc + 4];
                mma_f16(s[ni], qf[kt][0], qf[kt][1], qf[kt][2], qf[kt][3], b0, b1);
            }
        }

        // --- scale + causal mask + row max -----------------------------------
        const bool diag = (t == qt);
        float mt0 = -1e30f, mt1 = -1e30f;
#pragma unroll
        for (int ni = 0; ni < 8; ni++) {
            int kc = t * 64 + ni * 8 + 2 * lc;
#pragma unroll
            for (int e = 0; e < 4; e++) s[ni][e] *= 0.125f;
            if (diag) {
                if (kc     > q0) s[ni][0] = -1e30f;
                if (kc + 1 > q0) s[ni][1] = -1e30f;
                if (kc     > q1) s[ni][2] = -1e30f;
                if (kc + 1 > q1) s[ni][3] = -1e30f;
            }
            mt0 = fmaxf(mt0, fmaxf(s[ni][0], s[ni][1]));
            mt1 = fmaxf(mt1, fmaxf(s[ni][2], s[ni][3]));
        }
        mt0 = fmaxf(mt0, __shfl_xor_sync(0xffffffffu, mt0, 1));
        mt0 = fmaxf(mt0, __shfl_xor_sync(0xffffffffu, mt0, 2));
        mt1 = fmaxf(mt1, __shfl_xor_sync(0xffffffffu, mt1, 1));
        mt1 = fmaxf(mt1, __shfl_xor_sync(0xffffffffu, mt1, 2));

        float mn0 = fmaxf(m0, mt0), mn1 = fmaxf(m1, mt1);
        float cr0 = __expf(m0 - mn0), cr1 = __expf(m1 - mn1);
        m0 = mn0; m1 = mn1;
        l0 *= cr0; l1 *= cr1;
#pragma unroll
        for (int ni = 0; ni < 8; ni++) {
            o[ni][0] *= cr0; o[ni][1] *= cr0;
            o[ni][2] *= cr1; o[ni][3] *= cr1;
        }

        // --- P = exp(S - m) -> packed half2, warp-private smem rows ----------
        float ps0 = 0.0f, ps1 = 0.0f;
        const int pr0 = warp * 16 + lr;
#pragma unroll
        for (int ni = 0; ni < 8; ni++) {
            float p0 = __expf(s[ni][0] - m0);
            float p1 = __expf(s[ni][1] - m0);
            float p2 = __expf(s[ni][2] - m1);
            float p3 = __expf(s[ni][3] - m1);
            ps0 += p0 + p1; ps1 += p2 + p3;
            PQ[pr0 * FSTRW + ni * 4 + lc]       = pack_h2(p0, p1);
            PQ[(pr0 + 8) * FSTRW + ni * 4 + lc] = pack_h2(p2, p3);
        }
        ps0 += __shfl_xor_sync(0xffffffffu, ps0, 1);
        ps0 += __shfl_xor_sync(0xffffffffu, ps0, 2);
        ps1 += __shfl_xor_sync(0xffffffffu, ps1, 1);
        ps1 += __shfl_xor_sync(0xffffffffu, ps1, 2);
        l0 += ps0; l1 += ps1;
        __syncwarp();

        // --- O += P @ V ------------------------------------------------------
#pragma unroll
        for (int kk = 0; kk < 4; kk++) {
            unsigned pa0 = PQ[pr0 * FSTRW + kk * 8 + lc];
            unsigned pa1 = PQ[(pr0 + 8) * FSTRW + kk * 8 + lc];
            unsigned pa2 = PQ[pr0 * FSTRW + kk * 8 + lc + 4];
            unsigned pa3 = PQ[(pr0 + 8) * FSTRW + kk * 8 + lc + 4];
            const int kbase = kk * 16 + 2 * lc;
#pragma unroll
            for (int ni = 0; ni < 8; ni++) {
                const int n = ni * 8 + lr;
                unsigned b0 = (unsigned)Vu[(kbase)     * 72 + n]
                            | ((unsigned)Vu[(kbase + 1) * 72 + n] << 16);
                unsigned b1 = (unsigned)Vu[(kbase + 8) * 72 + n]
                            | ((unsigned)Vu[(kbase + 9) * 72 + n] << 16);
                mma_f16(o[ni], pa0, pa1, pa2, pa3, b0, b1);
            }
        }
        __syncthreads();   // before next tile restages K/V
    }

    // --- normalize + store ---------------------------------------------------
    float i0 = 1.0f / l0, i1 = 1.0f / l1;
#pragma unroll
    for (int ni = 0; ni < 8; ni++) {
        int col = ni * 8 + 2 * lc;
        *(float2*)(g_O + (bbase + q0) * DMODEL + hoff + col) =
            make_float2(o[ni][0] * i0, o[ni][1] * i0);
        *(float2*)(g_O + (bbase + q1) * DMODEL + hoff + col) =
            make_float2(o[ni][2] * i1, o[ni][3] * i1);
    }
}

// ---------------------------------------------------------------------------
// Launch
// ---------------------------------------------------------------------------
extern "C" void kernel_launch(void* const* d_in, const int* in_sizes, int n_in,
                              void* d_out, int out_size)
{
    const float* x  = (const float*)d_in[0];
    const float* wq = (const float*)d_in[1];
    const float* wk = (const float*)d_in[2];
    const float* wv = (const float*)d_in[3];
    const float* wo = (const float*)d_in[4];
    float* out = (float*)d_out;

    dim3 qkvgrid(DMODEL / 128, MTOT / 128, 3);   // (8, 64, 3)
    gemm_f16<<<qkvgrid, 256>>>(x, wq, wk, wv, nullptr, 0);

    dim3 agrid(SEQ / 64, NHEADS, BATCH);         // (32, 16, 4)
    flash_f16<<<agrid, 128>>>();

    dim3 ogrid(DMODEL / 128, MTOT / 128, 1);
    gemm_f16<<<ogrid, 256>>>(nullptr, wo, wo, wo, out, 1);
}

// round 5
// speedup vs baseline: 10.6127x; 1.4472x over previous
#include <cuda_runtime.h>
#include <cuda_fp16.h>
#include <cstdint>

#define BATCH   4
#define SEQ     2048
#define DMODEL  1024
#define NHEADS  16
#define DHEAD   64
#define MTOT    (BATCH * SEQ)

// ---------------------------------------------------------------------------
// Scratch (all fp16)
// ---------------------------------------------------------------------------
__device__ __half g_Xh[MTOT * DMODEL];
__device__ __half g_Wh[4][DMODEL * DMODEL];
__device__ __half g_Qh[MTOT * DMODEL];
__device__ __half g_Kh[MTOT * DMODEL];
__device__ __half g_Vh[MTOT * DMODEL];
__device__ __half g_Oh[MTOT * DMODEL];

// ---------------------------------------------------------------------------
// Helpers
// ---------------------------------------------------------------------------
__device__ __forceinline__ uint32_t smem_u32(const void* p) {
    uint32_t a;
    asm("{ .reg .u64 t; cvta.to.shared.u64 t, %1; cvt.u32.u64 %0, t; }"
        : "=r"(a) : "l"(p));
    return a;
}

#define CP_ASYNC(dst, src) \
    asm volatile("cp.async.cg.shared.global [%0], [%1], 16;" :: "r"(dst), "l"(src))
#define CP_COMMIT() asm volatile("cp.async.commit_group;")
#define CP_WAIT(n)  asm volatile("cp.async.wait_group %0;" :: "n"(n))

__device__ __forceinline__ void ldm_x4(unsigned& r0, unsigned& r1,
                                       unsigned& r2, unsigned& r3, uint32_t a) {
    asm volatile("ldmatrix.sync.aligned.m8n8.x4.shared.b16 {%0,%1,%2,%3}, [%4];"
                 : "=r"(r0), "=r"(r1), "=r"(r2), "=r"(r3) : "r"(a));
}
__device__ __forceinline__ void ldm_x4t(unsigned& r0, unsigned& r1,
                                        unsigned& r2, unsigned& r3, uint32_t a) {
    asm volatile("ldmatrix.sync.aligned.m8n8.x4.trans.shared.b16 {%0,%1,%2,%3}, [%4];"
                 : "=r"(r0), "=r"(r1), "=r"(r2), "=r"(r3) : "r"(a));
}

__device__ __forceinline__ void mma_f16(float c[4],
                                        unsigned a0, unsigned a1, unsigned a2, unsigned a3,
                                        unsigned b0, unsigned b1) {
    asm volatile(
        "mma.sync.aligned.m16n8k16.row.col.f32.f16.f16.f32 "
        "{%0,%1,%2,%3}, {%4,%5,%6,%7}, {%8,%9}, {%0,%1,%2,%3};"
        : "+f"(c[0]), "+f"(c[1]), "+f"(c[2]), "+f"(c[3])
        : "r"(a0), "r"(a1), "r"(a2), "r"(a3), "r"(b0), "r"(b1));
}

__device__ __forceinline__ unsigned pack_h2(float lo, float hi) {
    __half2 h = __floats2half2_rn(lo, hi);
    return *(unsigned*)&h;
}

// ---------------------------------------------------------------------------
// fp32 -> fp16 conversion (x and the 4 weights)
// ---------------------------------------------------------------------------
__global__ __launch_bounds__(256) void cvt_f2h(const float* __restrict__ src,
                                               int sel, int n)
{
    __half* dst = (sel == 0) ? g_Xh : g_Wh[sel - 1];
    int i = (blockIdx.x * 256 + threadIdx.x) * 8;
    if (i < n) {
        float4 a = *(const float4*)(src + i);
        float4 b = *(const float4*)(src + i + 4);
        uint4 o;
        o.x = pack_h2(a.x, a.y); o.y = pack_h2(a.z, a.w);
        o.z = pack_h2(b.x, b.y); o.w = pack_h2(b.z, b.w);
        *(uint4*)(dst + i) = o;
    }
}

// ---------------------------------------------------------------------------
// FP16 GEMM:  C[M,N] = A[M,K] * W[N,K]^T
// 128x128 tile, BK=32, 4-stage cp.async pipeline, ldmatrix fragments.
// Smem row = 32 halves padded to 40 (80 B) -> conflict-free ldmatrix.
// mode 0: A=g_Xh, W=g_Wh[z], C(half)=g_Qh/g_Kh/g_Vh per blockIdx.z
// mode 1: A=g_Oh, W=g_Wh[3], C(float)=outf
// ---------------------------------------------------------------------------
#define GSTAGE 20480                     // (A 10240 + B 10240) bytes per stage
#define GEMM_SMEM (4 * GSTAGE)           // 81920

__global__ __launch_bounds__(256) void gemm_h(float* __restrict__ outf, int mode)
{
    extern __shared__ char smem[];
    const int z = blockIdx.z;
    const __half* __restrict__ A = (mode == 0) ? g_Xh : g_Oh;
    const __half* __restrict__ W = (mode == 0) ? g_Wh[z] : g_Wh[3];

    const int tid  = threadIdx.x;
    const int lane = tid & 31;
    const int warp = tid >> 5;
    const int wm   = (warp >> 1) * 32;
    const int wn   = (warp & 1) * 64;
    const int lr   = lane >> 2;
    const int lc   = lane & 3;
    const int bm   = blockIdx.y * 128;
    const int bn   = blockIdx.x * 128;

    const uint32_t sb = smem_u32(smem);

    const int ldrow = tid >> 2;          // 0..63
    const int ldc16 = tid & 3;           // 0..3

    float acc[2][8][4];
#pragma unroll
    for (int mi = 0; mi < 2; mi++)
#pragma unroll
        for (int ni = 0; ni < 8; ni++)
#pragma unroll
            for (int e = 0; e < 4; e++) acc[mi][ni][e] = 0.0f;

    // ---- issue one k-chunk (c) into stage c&3 ------------------------------
    auto issue = [&](int c) {
        const int st = c & 3;
        const uint32_t sA = sb + st * GSTAGE;
        const uint32_t sB = sA + 10240;
#pragma unroll
        for (int i = 0; i < 2; i++) {
            int t   = tid + i * 256;
            int row = t >> 2;            // 0..127
            int c16 = t & 3;             // 0..3
            const __half* as = A + (size_t)(bm + row) * DMODEL + c * 32 + c16 * 8;
            const __half* ws = W + (size_t)(bn + row) * DMODEL + c * 32 + c16 * 8;
            CP_ASYNC(sA + row * 80 + c16 * 16, as);
            CP_ASYNC(sB + row * 80 + c16 * 16, ws);
        }
        (void)ldrow; (void)ldc16;
    };

    // ---- compute one k-chunk from stage st ---------------------------------
    auto compute = [&](int st) {
        const uint32_t sA = sb + st * GSTAGE;
        const uint32_t sB = sA + 10240;
#pragma unroll
        for (int ks = 0; ks < 2; ks++) {
            unsigned af[2][4];
#pragma unroll
            for (int mi = 0; mi < 2; mi++)
                ldm_x4(af[mi][0], af[mi][1], af[mi][2], af[mi][3],
                       sA + (wm + mi * 16 + (lane & 15)) * 80
                          + ((lane >> 4) * 8 + ks * 16) * 2);
#pragma unroll
            for (int nt = 0; nt < 4; nt++) {
                unsigned b0, b1, b2, b3;
                ldm_x4(b0, b1, b2, b3,
                       sB + (wn + nt * 16 + ((lane >> 4) * 8) + (lane & 7)) * 80
                          + (((lane >> 3) & 1) * 8 + ks * 16) * 2);
#pragma unroll
                for (int mi = 0; mi < 2; mi++) {
                    mma_f16(acc[mi][2 * nt],     af[mi][0], af[mi][1], af[mi][2], af[mi][3], b0, b1);
                    mma_f16(acc[mi][2 * nt + 1], af[mi][0], af[mi][1], af[mi][2], af[mi][3], b2, b3);
                }
            }
        }
    };

    // ---- pipeline ----------------------------------------------------------
#pragma unroll
    for (int s = 0; s < 3; s++) { issue(s); CP_COMMIT(); }

    for (int c = 0; c < 32; c++) {
        if (c < 30)       CP_WAIT(2);
        else if (c == 30) CP_WAIT(1);
        else              CP_WAIT(0);
        __syncthreads();
        if (c + 3 < 32) { issue(c + 3); CP_COMMIT(); }
        compute(c & 3);
    }

    // ---- epilogue ----------------------------------------------------------
    if (mode == 0) {
        __half* C = (z == 0) ? g_Qh : (z == 1) ? g_Kh : g_Vh;
#pragma unroll
        for (int mi = 0; mi < 2; mi++)
#pragma unroll
            for (int ni = 0; ni < 8; ni++) {
                int row = bm + wm + mi * 16 + lr;
                int col = bn + wn + ni * 8 + 2 * lc;
                *(__half2*)(C + (size_t)row * DMODEL + col) =
                    __floats2half2_rn(acc[mi][ni][0], acc[mi][ni][1]);
                *(__half2*)(C + (size_t)(row + 8) * DMODEL + col) =
                    __floats2half2_rn(acc[mi][ni][2], acc[mi][ni][3]);
            }
    } else {
#pragma unroll
        for (int mi = 0; mi < 2; mi++)
#pragma unroll
            for (int ni = 0; ni < 8; ni++) {
                int row = bm + wm + mi * 16 + lr;
                int col = bn + wn + ni * 8 + 2 * lc;
                *(float2*)(outf + (size_t)row * DMODEL + col) =
                    make_float2(acc[mi][ni][0], acc[mi][ni][1]);
                *(float2*)(outf + (size_t)(row + 8) * DMODEL + col) =
                    make_float2(acc[mi][ni][2], acc[mi][ni][3]);
            }
    }
}

// ---------------------------------------------------------------------------
// FP16 flash attention (causal). Br=64 (4 warps), Bc=64.
// cp.async double-buffered K/V; ldmatrix everywhere (trans for V).
// Smem rows = 64 halves padded to 72 (144 B).
// ---------------------------------------------------------------------------
#define FROWB 144
#define FTILE (64 * FROWB)               // 9216 bytes

__global__ __launch_bounds__(128) void flash_h()
{
    __shared__ __align__(16) char fsm[5 * FTILE];   // K0,K1,V0,V1,PQ = 46080 B

    const uint32_t sb = smem_u32(fsm);
    const uint32_t Kb0 = sb, Kb1 = sb + FTILE;
    const uint32_t Vb0 = sb + 2 * FTILE, Vb1 = sb + 3 * FTILE;
    const uint32_t Pb  = sb + 4 * FTILE;
    unsigned* Pw = (unsigned*)(fsm + 4 * FTILE);

    const int qt   = gridDim.x - 1 - blockIdx.x;   // heavy blocks first
    const int h    = blockIdx.y;
    const int b    = blockIdx.z;
    const int tid  = threadIdx.x;
    const int lane = tid & 31;
    const int warp = tid >> 5;
    const int lr   = lane >> 2;
    const int lc   = lane & 3;

    const size_t bbase = (size_t)b * SEQ;
    const size_t hoff  = (size_t)h * DHEAD;

    // ---- stage Q via cp.async, extract fragments ---------------------------
#pragma unroll
    for (int i = 0; i < 4; i++) {
        int t = tid + i * 128;
        int row = t >> 3, c16 = t & 7;
        CP_ASYNC(Pb + row * FROWB + c16 * 16,
                 g_Qh + (bbase + qt * 64 + row) * DMODEL + hoff + c16 * 8);
    }
    CP_COMMIT(); CP_WAIT(0);
    __syncthreads();

    unsigned qf[4][4];
#pragma unroll
    for (int ks = 0; ks < 4; ks++)
        ldm_x4(qf[ks][0], qf[ks][1], qf[ks][2], qf[ks][3],
               Pb + (warp * 16 + (lane & 15)) * FROWB
                  + ((lane >> 4) * 8 + ks * 16) * 2);
    __syncthreads();   // PQ now free for P

    auto issue_kv = [&](int t, int bi) {
        const uint32_t kb = bi ? Kb1 : Kb0;
        const uint32_t vb = bi ? Vb1 : Vb0;
#pragma unroll
        for (int i = 0; i < 4; i++) {
            int t2 = tid + i * 128;
            int row = t2 >> 3, c16 = t2 & 7;
            size_t g = (bbase + t * 64 + row) * DMODEL + hoff + c16 * 8;
            CP_ASYNC(kb + row * FROWB + c16 * 16, g_Kh + g);
            CP_ASYNC(vb + row * FROWB + c16 * 16, g_Vh + g);
        }
    };

    float o[8][4];
#pragma unroll
    for (int ni = 0; ni < 8; ni++)
#pragma unroll
        for (int e = 0; e < 4; e++) o[ni][e] = 0.0f;

    float m0 = -1e30f, m1 = -1e30f, l0 = 0.0f, l1 = 0.0f;
    const int q0 = qt * 64 + warp * 16 + lr;
    const int q1 = q0 + 8;

    issue_kv(0, 0); CP_COMMIT();

    for (int t = 0; t <= qt; t++) {
        if (t < qt) { issue_kv(t + 1, (t + 1) & 1); CP_COMMIT(); CP_WAIT(1); }
        else        { CP_WAIT(0); }
        __syncthreads();

        const uint32_t kb = (t & 1) ? Kb1 : Kb0;
        const uint32_t vb = (t & 1) ? Vb1 : Vb0;

        // --- S = Q @ K^T -----------------------------------------------------
        float s[8][4];
#pragma unroll
        for (int ni = 0; ni < 8; ni++)
#pragma unroll
            for (int e = 0; e < 4; e++) s[ni][e] = 0.0f;
#pragma unroll
        for (int ks = 0; ks < 4; ks++) {
#pragma unroll
            for (int nt = 0; nt < 4; nt++) {
                unsigned b0, b1, b2, b3;
                ldm_x4(b0, b1, b2, b3,
                       kb + (nt * 16 + ((lane >> 4) * 8) + (lane & 7)) * FROWB
                          + (((lane >> 3) & 1) * 8 + ks * 16) * 2);
                mma_f16(s[2 * nt],     qf[ks][0], qf[ks][1], qf[ks][2], qf[ks][3], b0, b1);
                mma_f16(s[2 * nt + 1], qf[ks][0], qf[ks][1], qf[ks][2], qf[ks][3], b2, b3);
            }
        }

        // --- scale + causal mask + row max -----------------------------------
        const bool diag = (t == qt);
        float mt0 = -1e30f, mt1 = -1e30f;
#pragma unroll
        for (int ni = 0; ni < 8; ni++) {
            int kc = t * 64 + ni * 8 + 2 * lc;
#pragma unroll
            for (int e = 0; e < 4; e++) s[ni][e] *= 0.125f;
            if (diag) {
                if (kc     > q0) s[ni][0] = -1e30f;
                if (kc + 1 > q0) s[ni][1] = -1e30f;
                if (kc     > q1) s[ni][2] = -1e30f;
                if (kc + 1 > q1) s[ni][3] = -1e30f;
            }
            mt0 = fmaxf(mt0, fmaxf(s[ni][0], s[ni][1]));
            mt1 = fmaxf(mt1, fmaxf(s[ni][2], s[ni][3]));
        }
        mt0 = fmaxf(mt0, __shfl_xor_sync(0xffffffffu, mt0, 1));
        mt0 = fmaxf(mt0, __shfl_xor_sync(0xffffffffu, mt0, 2));
        mt1 = fmaxf(mt1, __shfl_xor_sync(0xffffffffu, mt1, 1));
        mt1 = fmaxf(mt1, __shfl_xor_sync(0xffffffffu, mt1, 2));

        float mn0 = fmaxf(m0, mt0), mn1 = fmaxf(m1, mt1);
        float cr0 = __expf(m0 - mn0), cr1 = __expf(m1 - mn1);
        m0 = mn0; m1 = mn1;
        l0 *= cr0; l1 *= cr1;
#pragma unroll
        for (int ni = 0; ni < 8; ni++) {
            o[ni][0] *= cr0; o[ni][1] *= cr0;
            o[ni][2] *= cr1; o[ni][3] *= cr1;
        }

        // --- P = exp(S - m) -> warp-private smem rows ------------------------
        float ps0 = 0.0f, ps1 = 0.0f;
        const int pr0 = warp * 16 + lr;
#pragma unroll
        for (int ni = 0; ni < 8; ni++) {
            float p0 = __expf(s[ni][0] - m0);
            float p1 = __expf(s[ni][1] - m0);
            float p2 = __expf(s[ni][2] - m1);
            float p3 = __expf(s[ni][3] - m1);
            ps0 += p0 + p1; ps1 += p2 + p3;
            Pw[pr0 * 36 + ni * 4 + lc]       = pack_h2(p0, p1);
            Pw[(pr0 + 8) * 36 + ni * 4 + lc] = pack_h2(p2, p3);
        }
        ps0 += __shfl_xor_sync(0xffffffffu, ps0, 1);
        ps0 += __shfl_xor_sync(0xffffffffu, ps0, 2);
        ps1 += __shfl_xor_sync(0xffffffffu, ps1, 1);
        ps1 += __shfl_xor_sync(0xffffffffu, ps1, 2);
        l0 += ps0; l1 += ps1;
        __syncwarp();

        // --- O += P @ V  (P via ldmatrix, V via ldmatrix.trans) --------------
#pragma unroll
        for (int kk = 0; kk < 4; kk++) {
            unsigned pa0, pa1, pa2, pa3;
            ldm_x4(pa0, pa1, pa2, pa3,
                   Pb + (warp * 16 + (lane & 15)) * FROWB
                      + ((lane >> 4) * 8 + kk * 16) * 2);
#pragma unroll
            for (int nt = 0; nt < 4; nt++) {
                unsigned v0, v1, v2, v3;
                ldm_x4t(v0, v1, v2, v3,
                        vb + (kk * 16 + ((lane >> 3) & 1) * 8 + (lane & 7)) * FROWB
                           + (nt * 16 + (lane >> 4) * 8) * 2);
                mma_f16(o[2 * nt],     pa0, pa1, pa2, pa3, v0, v1);
                mma_f16(o[2 * nt + 1], pa0, pa1, pa2, pa3, v2, v3);
            }
        }
        __syncthreads();   // protect K/V buffer reuse + P rewrite
    }

    // --- normalize + store (fp16) --------------------------------------------
    float i0 = 1.0f / l0, i1 = 1.0f / l1;
#pragma unroll
    for (int ni = 0; ni < 8; ni++) {
        int col = ni * 8 + 2 * lc;
        *(__half2*)(g_Oh + (bbase + q0) * DMODEL + hoff + col) =
            __floats2half2_rn(o[ni][0] * i0, o[ni][1] * i0);
        *(__half2*)(g_Oh + (bbase + q1) * DMODEL + hoff + col) =
            __floats2half2_rn(o[ni][2] * i1, o[ni][3] * i1);
    }
}

// ---------------------------------------------------------------------------
// Launch
// ---------------------------------------------------------------------------
extern "C" void kernel_launch(void* const* d_in, const int* in_sizes, int n_in,
                              void* d_out, int out_size)
{
    const float* x  = (const float*)d_in[0];
    const float* wq = (const float*)d_in[1];
    const float* wk = (const float*)d_in[2];
    const float* wv = (const float*)d_in[3];
    const float* wo = (const float*)d_in[4];
    float* out = (float*)d_out;

    static int attr_done = 0;
    if (!attr_done) {
        cudaFuncSetAttribute(gemm_h, cudaFuncAttributeMaxDynamicSharedMemorySize, GEMM_SMEM);
        attr_done = 1;
    }

    const int NX = MTOT * DMODEL;        // 8388608
    const int NW = DMODEL * DMODEL;      // 1048576
    cvt_f2h<<<NX / 2048, 256>>>(x,  0, NX);
    cvt_f2h<<<NW / 2048, 256>>>(wq, 1, NW);
    cvt_f2h<<<NW / 2048, 256>>>(wk, 2, NW);
    cvt_f2h<<<NW / 2048, 256>>>(wv, 3, NW);
    cvt_f2h<<<NW / 2048, 256>>>(wo, 4, NW);

    dim3 qkvgrid(DMODEL / 128, MTOT / 128, 3);   // (8, 64, 3)
    gemm_h<<<qkvgrid, 256, GEMM_SMEM>>>(nullptr, 0);

    dim3 agrid(SEQ / 64, NHEADS, BATCH);         // (32, 16, 4)
    flash_h<<<agrid, 128>>>();

    dim3 ogrid(DMODEL / 128, MTOT / 128, 1);
    gemm_h<<<ogrid, 256, GEMM_SMEM>>>(out, 1);
}